// round 3
// baseline (speedup 1.0000x reference)
#include <cuda_runtime.h>
#include <cuda_bf16.h>
#include <mma.h>
#include <math.h>
#include <stdint.h>

using namespace nvcuda;

// S=40, B=32, T=40, E=256, H=512, V=50000. decoder rows (T-1)*B = 1248 (pad 1280)
#define NTILES 391
#define DNB 128
#define ENB 128

// ---------------- static device scratch ----------------
__device__ __nv_bfloat16 g_srceb [1280*256];
__device__ __nv_bfloat16 g_srcerb[1280*256];
__device__ __nv_bfloat16 g_tgteb [1280*256];
__device__ __nv_bfloat16 g_wifb  [2048*256];
__device__ __nv_bfloat16 g_wibb  [2048*256];
__device__ __nv_bfloat16 g_widb  [2048*256];
__device__ __nv_bfloat16 g_wattb [512*1024];
__device__ float g_xf   [1280*2048];
__device__ float g_xb   [1280*2048];
__device__ float g_xe   [1280*2048];
__device__ float g_henc [2*2*32*512];     // [par][dir][b][512]
__device__ float g_cenc [2*32*512];       // [dir][b][512]
__device__ float g_ench [32*40*1024];     // [b][s][2H] fp32
__device__ __nv_bfloat16 g_enchb[32*40*1024];
__device__ float g_encp [32*40*512];
__device__ float g_hcc  [32*1024];
__device__ float g_ccc  [32*1024];
__device__ float g_hcat [2*32*1024];      // [par][b][ h(512) | o_prev(512) ]
__device__ float g_cdec [32*512];
__device__ float g_kcat [32*1536];        // [b][ h(512) | ctx(1024) ]
__device__ float g_Wdr  [2048*1024];      // [Whh | Wih_o]
__device__ __nv_bfloat16 g_outsb[1280*512];
__device__ __nv_bfloat16 g_wvb  [50048ull*512];
__device__ float g_pmax [1248*NTILES];
__device__ float g_psum [1248*NTILES];
__device__ float g_pick [1248];
__device__ float g_plogp[1248];

// grid barrier state (g_arr returns to 0 after each barrier; g_rel monotonic)
__device__ unsigned g_arr;
__device__ unsigned g_rel;

__device__ __forceinline__ float sigf(float x){ return 1.f/(1.f+expf(-x)); }

__device__ __forceinline__ void gridbar(unsigned &mygen, unsigned NB){
    __syncthreads();
    if (threadIdx.x == 0){
        __threadfence();
        unsigned old = atomicAdd(&g_arr, 1);
        if (old == NB-1){
            atomicExch(&g_arr, 0);
            __threadfence();
            atomicAdd(&g_rel, 1);
        } else {
            unsigned target = mygen + 1;
            while ((int)(*(volatile unsigned*)&g_rel - target) < 0) __nanosleep(64);
        }
    }
    __syncthreads();
    mygen++;
}

// ---------------- prep: weights repack + zero states ----------------
__global__ void k_prep(const float* dWih, const float* dWhh, const float* eWif,
                       const float* eWib, const float* Watt){
    size_t stride = (size_t)gridDim.x*blockDim.x;
    size_t id0 = (size_t)blockIdx.x*blockDim.x + threadIdx.x;
    for (size_t i=id0; i<2048ull*1024; i+=stride){
        int n = (int)(i>>10), k = (int)(i&1023);
        g_Wdr[i] = (k<512) ? dWhh[(size_t)n*512+k] : dWih[(size_t)n*768 + 256 + (k-512)];
    }
    for (size_t i=id0; i<2048ull*256; i+=stride){
        int n = (int)(i>>8), k = (int)(i&255);
        g_wifb[i] = __float2bfloat16(eWif[i]);
        g_wibb[i] = __float2bfloat16(eWib[i]);
        g_widb[i] = __float2bfloat16(dWih[(size_t)n*768 + k]);
    }
    for (size_t i=id0; i<512ull*1024; i+=stride) g_wattb[i] = __float2bfloat16(Watt[i]);
    for (size_t i=id0; i<2ull*2*32*512; i+=stride) g_henc[i]=0.f;
    for (size_t i=id0; i<2ull*32*512;   i+=stride) g_cenc[i]=0.f;
    for (size_t i=id0; i<32ull*512;     i+=stride) g_cdec[i]=0.f;
    for (size_t i=id0; i<32ull*512;     i+=stride)
        g_hcat[(i>>9)*1024 + 512 + (i&511)] = 0.f;          // o0 = 0 (buffer 0)
    for (size_t i=id0; i<32ull*512;     i+=stride)
        g_outsb[1248ull*512 + i] = __float2bfloat16(0.f);   // pad rows
}

__global__ void k_wvb(const float* Wv){
    size_t stride = (size_t)gridDim.x*blockDim.x;
    for (size_t i=(size_t)blockIdx.x*blockDim.x+threadIdx.x; i<50048ull*512; i+=stride){
        size_t v = i >> 9;
        g_wvb[i] = __float2bfloat16(v < 50000 ? Wv[i] : 0.f);
    }
}

__global__ void k_gather(const int* src, const int* tgt, const float* se, const float* te){
    size_t stride = (size_t)gridDim.x*blockDim.x;
    for (size_t i=(size_t)blockIdx.x*blockDim.x+threadIdx.x; i<(size_t)(1280+1280+1248)*256; i+=stride){
        int k = (int)(i & 255); size_t m = i >> 8;
        if (m < 1280) g_srceb[m*256+k] = __float2bfloat16(se[(size_t)src[m]*256+k]);
        else if (m < 2560){
            size_t mm = m-1280; int tt=(int)(mm>>5), bb=(int)(mm&31);
            g_srcerb[mm*256+k] = __float2bfloat16(se[(size_t)src[(39-tt)*32+bb]*256+k]);
        } else {
            size_t mm = m-2560;
            g_tgteb[mm*256+k] = __float2bfloat16(te[(size_t)tgt[mm]*256+k]);
        }
    }
}

// ---------------- bf16 wmma GEMM: C[M][N] = A[M][K] @ W[N][K]^T (+bias), tiles 128x128 ----------------
__global__ void __launch_bounds__(256) k_gemmb(const __nv_bfloat16* __restrict__ A,
        const __nv_bfloat16* __restrict__ W, const float* __restrict__ bias,
        float* __restrict__ C, int N, int K){
    extern __shared__ float ls[];
    int m0 = blockIdx.x*128, n0 = blockIdx.y*128;
    int w = threadIdx.x>>5, wm = w>>2, wn = w&3;
    wmma::fragment<wmma::matrix_a,16,16,16,__nv_bfloat16,wmma::row_major> af[4];
    wmma::fragment<wmma::matrix_b,16,16,16,__nv_bfloat16,wmma::col_major> bf[2];
    wmma::fragment<wmma::accumulator,16,16,16,float> cf[4][2];
    #pragma unroll
    for (int i=0;i<4;i++)
        #pragma unroll
        for (int j=0;j<2;j++) wmma::fill_fragment(cf[i][j], 0.f);
    const __nv_bfloat16* Ab = A + (size_t)(m0 + wm*64)*K;
    const __nv_bfloat16* Bb = W + (size_t)(n0 + wn*32)*K;
    for (int k=0;k<K;k+=16){
        #pragma unroll
        for (int i=0;i<4;i++) wmma::load_matrix_sync(af[i], Ab + (size_t)i*16*K + k, K);
        #pragma unroll
        for (int j=0;j<2;j++) wmma::load_matrix_sync(bf[j], Bb + (size_t)j*16*K + k, K);
        #pragma unroll
        for (int i=0;i<4;i++)
            #pragma unroll
            for (int j=0;j<2;j++) wmma::mma_sync(cf[i][j], af[i], bf[j], cf[i][j]);
    }
    #pragma unroll
    for (int i=0;i<4;i++)
        #pragma unroll
        for (int j=0;j<2;j++)
            wmma::store_matrix_sync(&ls[(wm*64+i*16)*132 + wn*32 + j*16], cf[i][j], 132, wmma::mem_row_major);
    __syncthreads();
    for (int idx=threadIdx.x; idx<128*128; idx+=256){
        int r=idx>>7, cc=idx&127;
        C[(size_t)(m0+r)*N + n0+cc] = ls[r*132+cc] + (bias ? bias[n0+cc] : 0.f);
    }
}

// ---------------- fp32 GEMM (small projections Wh/Wc) ----------------
__global__ void __launch_bounds__(256) k_gemm(const float* A, int lda, const float* W, int ldw,
        const float* bias, float* C, int ldc, int M, int N, int K){
    int m0 = blockIdx.x*64, n0 = blockIdx.y*64;
    int tid = threadIdx.x, tx = tid&15, ty = tid>>4;
    __shared__ float As[64][33], Bs[64][33];
    float acc[4][4] = {};
    for (int k0=0; k0<K; k0+=32){
        #pragma unroll
        for (int p=0;p<8;p++){
            int idx = tid + p*256; int r = idx>>5, kk = idx&31;
            As[r][kk] = (m0+r < M) ? A[(size_t)(m0+r)*lda + k0 + kk] : 0.f;
            Bs[r][kk] = (n0+r < N) ? W[(size_t)(n0+r)*ldw + k0 + kk] : 0.f;
        }
        __syncthreads();
        #pragma unroll
        for (int kk=0;kk<32;kk++){
            float av[4], bv[4];
            #pragma unroll
            for (int i=0;i<4;i++) av[i] = As[ty*4+i][kk];
            #pragma unroll
            for (int j=0;j<4;j++) bv[j] = Bs[tx*4+j][kk];
            #pragma unroll
            for (int i=0;i<4;i++)
                #pragma unroll
                for (int j=0;j<4;j++) acc[i][j] += av[i]*bv[j];
        }
        __syncthreads();
    }
    #pragma unroll
    for (int i=0;i<4;i++){
        int m = m0 + ty*4 + i; if (m >= M) continue;
        #pragma unroll
        for (int j=0;j<4;j++){
            int n = n0 + tx*4 + j; if (n >= N) continue;
            C[(size_t)m*ldc + n] = acc[i][j] + (bias ? bias[n] : 0.f);
        }
    }
}

// ---------------- persistent encoder: 40 steps, 1 grid barrier/step ----------------
__global__ void __launch_bounds__(256) k_encoder(const float* __restrict__ Whf,
                                                 const float* __restrict__ Whb){
    __shared__ float Hs[64][33];
    __shared__ float Ws[32][64];
    int tid = threadIdx.x, blk = blockIdx.x;
    int dir = blk>>6, j0 = (blk&63)*8;
    const float* W = dir ? Whb : Whf;
    const float* xbase = dir ? g_xb : g_xf;
    unsigned mygen = *(volatile unsigned*)&g_rel;
    int b = tid&31, u = tid>>5;
    for (int t=0;t<40;t++){
        int par = t&1;
        const float* hin = g_henc + (size_t)(par*2+dir)*32*512;
        float a0=0,a1=0,a2=0,a3=0;
        for (int c=0;c<8;c++){
            int k0 = c*64;
            #pragma unroll
            for (int p=0;p<8;p++){
                int idx=tid+p*256; int kk=idx>>5, bb=idx&31;
                Hs[kk][bb] = __ldcg(&hin[bb*512 + k0+kk]);
            }
            #pragma unroll
            for (int p=0;p<8;p++){
                int idx=tid+p*256; int r=idx>>6, kk=idx&63;
                Ws[r][kk] = W[(size_t)((r>>3)*512 + j0 + (r&7))*512 + k0+kk];
            }
            __syncthreads();
            #pragma unroll
            for (int kk=0;kk<64;kk++){
                float h = Hs[kk][b];
                a0 += h*Ws[u][kk];
                a1 += h*Ws[8+u][kk];
                a2 += h*Ws[16+u][kk];
                a3 += h*Ws[24+u][kk];
            }
            __syncthreads();
        }
        int j = j0+u;
        const float* xr = xbase + ((size_t)t*32+b)*2048;
        float gi = sigf (a0 + xr[j]);
        float gf = sigf (a1 + xr[512+j]);
        float gg = tanhf(a2 + xr[1024+j]);
        float go = sigf (a3 + xr[1536+j]);
        float cc = g_cenc[(size_t)(dir*32+b)*512 + j];
        float cn = gf*cc + gi*gg;
        g_cenc[(size_t)(dir*32+b)*512 + j] = cn;
        float hn = go*tanhf(cn);
        __stcg(&g_henc[((size_t)((1-par)*2+dir)*32 + b)*512 + j], hn);
        int s = dir ? (39-t) : t;
        size_t eo = ((size_t)b*40+s)*1024 + dir*512 + j;
        g_ench[eo]  = hn;
        g_enchb[eo] = __float2bfloat16(hn);
        gridbar(mygen, ENB);
    }
}

__global__ void k_mkcat(){
    int i = blockIdx.x*blockDim.x + threadIdx.x;
    if (i < 32*1024){
        int b = i>>10, k = i&1023; int dir = k>>9, kk = k&511;
        g_hcc[i] = g_henc[((size_t)(0*2+dir)*32 + b)*512 + kk];
        g_ccc[i] = g_cenc[((size_t)dir*32 + b)*512 + kk];
    }
}

// ---------------- persistent decoder: 39 steps x (gates | attention | comb) ----------------
__global__ void __launch_bounds__(256) k_decoder(const float* __restrict__ masks,
                                                 const float* __restrict__ Wc){
    __shared__ float As[128][33];
    __shared__ float Ws[16][128];
    __shared__ float Rs[32][4][4];
    __shared__ float hv[512];
    __shared__ float sc[40];
    int tid = threadIdx.x, blk = blockIdx.x;
    unsigned mygen = *(volatile unsigned*)&g_rel;
    int b = tid&31, u = (tid>>5)&3, kh = tid>>7;
    for (int t=0;t<39;t++){
        int par = t&1;
        // ---- phase 1: gates + cell ----
        {
            const float* hin = g_hcat + (size_t)par*32*1024;
            int j0 = blk*4;
            float a0=0,a1=0,a2=0,a3=0;
            for (int c=0;c<8;c++){
                #pragma unroll
                for (int p=0;p<16;p++){
                    int idx = tid + p*256;
                    int kk = idx>>5, bb = idx&31;
                    int kg = (kk<64) ? (c*64+kk) : (512 + c*64 + (kk-64));
                    As[kk][bb] = __ldcg(&hin[bb*1024 + kg]);
                }
                #pragma unroll
                for (int p=0;p<8;p++){
                    int idx = tid + p*256;
                    int r = idx>>7, kk = idx&127;
                    int kg = (kk<64) ? (c*64+kk) : (512 + c*64 + (kk-64));
                    Ws[r][kk] = g_Wdr[(size_t)((r>>2)*512 + j0 + (r&3))*1024 + kg];
                }
                __syncthreads();
                int kb = kh*64;
                #pragma unroll
                for (int kk=0;kk<64;kk++){
                    float a = As[kb+kk][b];
                    a0 += a*Ws[u][kb+kk];
                    a1 += a*Ws[4+u][kb+kk];
                    a2 += a*Ws[8+u][kb+kk];
                    a3 += a*Ws[12+u][kb+kk];
                }
                __syncthreads();
            }
            if (kh==1){ Rs[b][u][0]=a0; Rs[b][u][1]=a1; Rs[b][u][2]=a2; Rs[b][u][3]=a3; }
            __syncthreads();
            if (kh==0){
                a0 += Rs[b][u][0]; a1 += Rs[b][u][1]; a2 += Rs[b][u][2]; a3 += Rs[b][u][3];
                int j = j0 + u;
                const float* xr = g_xe + ((size_t)t*32 + b)*2048;
                float gi = sigf (a0 + xr[j]);
                float gf = sigf (a1 + xr[512+j]);
                float gg = tanhf(a2 + xr[1024+j]);
                float go = sigf (a3 + xr[1536+j]);
                float cc = g_cdec[b*512+j];
                float cn = gf*cc + gi*gg;
                g_cdec[b*512+j] = cn;
                float hn = go*tanhf(cn);
                __stcg(&g_kcat[(size_t)b*1536 + j], hn);
                __stcg(&g_hcat[(size_t)(1-par)*32768 + (size_t)b*1024 + j], hn);
            }
        }
        gridbar(mygen, DNB);
        // ---- phase 2: attention (blocks 0..31, one batch each) ----
        if (blk < 32){
            int bb = blk;
            for (int i=tid;i<512;i+=256) hv[i] = __ldcg(&g_kcat[(size_t)bb*1536 + i]);
            __syncthreads();
            int lane = tid&31, w = tid>>5;
            #pragma unroll
            for (int q=0;q<5;q++){
                int s = w*5+q;
                const float* ep = g_encp + ((size_t)bb*40 + s)*512;
                float p = 0.f;
                for (int k=lane;k<512;k+=32) p += ep[k]*hv[k];
                #pragma unroll
                for (int o=16;o;o>>=1) p += __shfl_down_sync(0xffffffffu, p, o);
                if (!lane) sc[s] = (masks[bb*40 + s] > 0.f) ? -INFINITY : p;
            }
            __syncthreads();
            if (tid == 0){
                float m = -INFINITY;
                for (int s=0;s<40;s++) m = fmaxf(m, sc[s]);
                float sum = 0.f;
                for (int s=0;s<40;s++){ float e = expf(sc[s]-m); sc[s]=e; sum+=e; }
                float inv = 1.f/sum;
                for (int s=0;s<40;s++) sc[s] *= inv;
            }
            __syncthreads();
            for (int jj=tid;jj<1024;jj+=256){
                float acc = 0.f;
                #pragma unroll 8
                for (int s=0;s<40;s++) acc += sc[s]*g_ench[((size_t)bb*40 + s)*1024 + jj];
                __stcg(&g_kcat[(size_t)bb*1536 + 512 + jj], acc);
            }
        }
        gridbar(mygen, DNB);
        // ---- phase 3: o_t = tanh([h|ctx] @ Wcomb^T) ----
        {
            int n0 = blk*4;
            float acc = 0.f;
            for (int c=0;c<12;c++){
                #pragma unroll
                for (int p=0;p<16;p++){
                    int idx = tid + p*256;
                    int kk = idx>>5, bb2 = idx&31;
                    int kg = (kk<64) ? (c*64+kk) : (768 + c*64 + (kk-64));
                    As[kk][bb2] = __ldcg(&g_kcat[(size_t)bb2*1536 + kg]);
                }
                #pragma unroll
                for (int p=0;p<2;p++){
                    int idx = tid + p*256;
                    int r = idx>>7, kk = idx&127;
                    int kg = (kk<64) ? (c*64+kk) : (768 + c*64 + (kk-64));
                    Ws[r][kk] = Wc[(size_t)(n0+r)*1536 + kg];
                }
                __syncthreads();
                int kb = kh*64;
                #pragma unroll
                for (int kk=0;kk<64;kk++) acc += As[kb+kk][b]*Ws[u][kb+kk];
                __syncthreads();
            }
            if (kh==1) Rs[b][u][0] = acc;
            __syncthreads();
            if (kh==0){
                float v = tanhf(acc + Rs[b][u][0]);
                int n = n0 + u;
                __stcg(&g_hcat[(size_t)(1-par)*32768 + (size_t)b*1024 + 512 + n], v);
                g_outsb[((size_t)t*32+b)*512 + n] = __float2bfloat16(v);
            }
        }
        gridbar(mygen, DNB);
    }
}

// ---------------- fused vocab GEMM (bf16 wmma, 128x128 tiles) + partial lse + pick ----------------
__global__ void __launch_bounds__(256) k_vocab(const int* __restrict__ tgt){
    extern __shared__ float ls[];
    int vt = blockIdx.x, rt = blockIdx.y;
    int w = threadIdx.x>>5, wm = w>>2, wn = w&3;
    wmma::fragment<wmma::matrix_a,16,16,16,__nv_bfloat16,wmma::row_major> af[4];
    wmma::fragment<wmma::matrix_b,16,16,16,__nv_bfloat16,wmma::col_major> bf[2];
    wmma::fragment<wmma::accumulator,16,16,16,float> cf[4][2];
    #pragma unroll
    for (int i=0;i<4;i++)
        #pragma unroll
        for (int j=0;j<2;j++) wmma::fill_fragment(cf[i][j], 0.f);
    const __nv_bfloat16* Ab = g_outsb + ((size_t)rt*128 + wm*64)*512;
    const __nv_bfloat16* Bb = g_wvb   + ((size_t)vt*128 + wn*32)*512;
    for (int k=0;k<512;k+=16){
        #pragma unroll
        for (int i=0;i<4;i++) wmma::load_matrix_sync(af[i], Ab + (size_t)i*16*512 + k, 512);
        #pragma unroll
        for (int j=0;j<2;j++) wmma::load_matrix_sync(bf[j], Bb + (size_t)j*16*512 + k, 512);
        #pragma unroll
        for (int i=0;i<4;i++)
            #pragma unroll
            for (int j=0;j<2;j++) wmma::mma_sync(cf[i][j], af[i], bf[j], cf[i][j]);
    }
    #pragma unroll
    for (int i=0;i<4;i++)
        #pragma unroll
        for (int j=0;j<2;j++)
            wmma::store_matrix_sync(&ls[(wm*64+i*16)*132 + wn*32 + j*16], cf[i][j], 132, wmma::mem_row_major);
    __syncthreads();
    int tid = threadIdx.x;
    if (tid < 128){
        int m = rt*128 + tid;
        if (m < 1248){
            int v0 = vt*128;
            int valid = min(128, 50000 - v0);
            float mx = -INFINITY;
            for (int c=0;c<valid;c++) mx = fmaxf(mx, ls[tid*132+c]);
            float s = 0.f;
            for (int c=0;c<valid;c++) s += expf(ls[tid*132+c]-mx);
            g_pmax[(size_t)m*NTILES + vt] = mx;
            g_psum[(size_t)m*NTILES + vt] = s;
            int tv = tgt[m + 32];
            if (tv >= v0 && tv < v0+valid) g_pick[m] = ls[tid*132 + tv - v0];
        }
    }
}

__global__ void k_lse(const int* tgt){
    int m = blockIdx.x*blockDim.x + threadIdx.x;
    if (m >= 1248) return;
    float mx = -INFINITY, s = 0.f;
    for (int j=0;j<NTILES;j++){
        float pm = g_pmax[(size_t)m*NTILES + j], ps = g_psum[(size_t)m*NTILES + j];
        if (pm > mx){ s = s*expf(mx-pm) + ps; mx = pm; }
        else s += ps*expf(pm-mx);
    }
    float lse = mx + logf(s);
    int tv = tgt[m + 32];
    g_plogp[m] = (tv != 0) ? (g_pick[m] - lse) : 0.f;
}

__global__ void k_out(float* out){
    int b = threadIdx.x;
    if (b < 32){
        float s = 0.f;
        for (int t=0;t<39;t++) s += g_plogp[t*32 + b];
        out[b] = s;
    }
}

// ---------------- launch ----------------
extern "C" void kernel_launch(void* const* d_in, const int* in_sizes, int n_in,
                              void* d_out, int out_size){
    const int*   src   = (const int*)d_in[0];
    const int*   tgt   = (const int*)d_in[1];
    const float* masks = (const float*)d_in[2];
    const float* se    = (const float*)d_in[3];
    const float* te    = (const float*)d_in[4];
    const float* eWif  = (const float*)d_in[5];
    const float* eWhf  = (const float*)d_in[6];
    const float* ebf   = (const float*)d_in[7];
    const float* eWib  = (const float*)d_in[8];
    const float* eWhb  = (const float*)d_in[9];
    const float* ebb   = (const float*)d_in[10];
    const float* dWih  = (const float*)d_in[11];
    const float* dWhh  = (const float*)d_in[12];
    const float* db    = (const float*)d_in[13];
    const float* Wh    = (const float*)d_in[14];
    const float* Wc    = (const float*)d_in[15];
    const float* Watt  = (const float*)d_in[16];
    const float* Wcomb = (const float*)d_in[17];
    const float* Wv    = (const float*)d_in[18];

    __nv_bfloat16 *p_srceb,*p_srcerb,*p_tgteb,*p_wifb,*p_wibb,*p_widb,*p_wattb,*p_enchb;
    float *p_xf,*p_xb,*p_xe,*p_encp,*p_hcc,*p_ccc,*p_hcat,*p_cdec;
    cudaGetSymbolAddress((void**)&p_srceb,  g_srceb);
    cudaGetSymbolAddress((void**)&p_srcerb, g_srcerb);
    cudaGetSymbolAddress((void**)&p_tgteb,  g_tgteb);
    cudaGetSymbolAddress((void**)&p_wifb,   g_wifb);
    cudaGetSymbolAddress((void**)&p_wibb,   g_wibb);
    cudaGetSymbolAddress((void**)&p_widb,   g_widb);
    cudaGetSymbolAddress((void**)&p_wattb,  g_wattb);
    cudaGetSymbolAddress((void**)&p_enchb,  g_enchb);
    cudaGetSymbolAddress((void**)&p_xf,     g_xf);
    cudaGetSymbolAddress((void**)&p_xb,     g_xb);
    cudaGetSymbolAddress((void**)&p_xe,     g_xe);
    cudaGetSymbolAddress((void**)&p_encp,   g_encp);
    cudaGetSymbolAddress((void**)&p_hcc,    g_hcc);
    cudaGetSymbolAddress((void**)&p_ccc,    g_ccc);
    cudaGetSymbolAddress((void**)&p_hcat,   g_hcat);
    cudaGetSymbolAddress((void**)&p_cdec,   g_cdec);

    cudaFuncSetAttribute(k_gemmb, cudaFuncAttributeMaxDynamicSharedMemorySize, 128*132*4);
    cudaFuncSetAttribute(k_vocab, cudaFuncAttributeMaxDynamicSharedMemorySize, 128*132*4);

    k_prep<<<1024,256>>>(dWih, dWhh, eWif, eWib, Watt);
    k_wvb<<<2048,256>>>(Wv);
    k_gather<<<512,256>>>(src, tgt, se, te);

    // input-side GEMMs (bf16 tensor cores)
    k_gemmb<<<dim3(10,16),256,128*132*4>>>(p_srceb,  p_wifb, ebf, p_xf, 2048, 256);
    k_gemmb<<<dim3(10,16),256,128*132*4>>>(p_srcerb, p_wibb, ebb, p_xb, 2048, 256);
    k_gemmb<<<dim3(10,16),256,128*132*4>>>(p_tgteb,  p_widb, db,  p_xe, 2048, 256);

    k_encoder<<<ENB,256>>>(eWhf, eWhb);

    k_mkcat<<<128,256>>>();
    k_gemm<<<dim3(1,8),256>>>(p_hcc, 1024, Wh, 1024, nullptr, p_hcat, 1024, 32, 512, 1024);
    k_gemm<<<dim3(1,8),256>>>(p_ccc, 1024, Wc, 1024, nullptr, p_cdec, 512,  32, 512, 1024);
    k_gemmb<<<dim3(10,4),256,128*132*4>>>(p_enchb, p_wattb, nullptr, p_encp, 512, 1024);

    k_decoder<<<DNB,256>>>(masks, Wcomb);

    k_vocab<<<dim3(NTILES,10),256,128*132*4>>>(tgt);
    k_lse<<<10,128>>>(tgt);
    k_out<<<1,32>>>((float*)d_out);
}

// round 4
// speedup vs baseline: 1.7554x; 1.7554x over previous
#include <cuda_runtime.h>
#include <cuda_bf16.h>
#include <mma.h>
#include <math.h>
#include <stdint.h>

using namespace nvcuda;

// S=40, B=32, T=40, E=256, H=512, V=50000; decoder rows 1248 (pad 1280)
#define NTILES 391

// ---------------- static device scratch ----------------
// transposed layouts: state is [feature][batch=32] so lane==batch is coalesced
__device__ __nv_bfloat16 g_srceb [1280*256];
__device__ __nv_bfloat16 g_srcerb[1280*256];
__device__ __nv_bfloat16 g_tgteb [1280*256];
__device__ __nv_bfloat16 g_wifb  [2048*256];
__device__ __nv_bfloat16 g_wibb  [2048*256];
__device__ __nv_bfloat16 g_widb  [2048*256];
__device__ __nv_bfloat16 g_wattb [512*1024];
__device__ float g_xf   [40*2048*32];   // [t][2048][32]
__device__ float g_xb   [40*2048*32];
__device__ float g_xe   [40*2048*32];
__device__ float g_henc [2*2*512*32];   // [par][dir][512][32]
__device__ float g_cenc [2*512*32];     // [dir][512][32]
__device__ float g_ench [32*40*1024];   // [b][s][2H] fp32 (for ctx)
__device__ __nv_bfloat16 g_enchb[1280*1024]; // rows m=b*40+s
__device__ float g_encp [1280*512];     // rows m=b*40+s
__device__ float g_hcc  [32*1024];
__device__ float g_ccc  [32*1024];
__device__ float g_hcat [2*1024*32];    // [par][ h(512)|o_prev(512) ][32]
__device__ float g_cdec [512*32];
__device__ float g_kcat [1536*32];      // [ h(512)|ctx(1024) ][32]
__device__ float g_Wdr  [2048*1024];    // [Whh | Wih_o]
__device__ __nv_bfloat16 g_outsb[1280*512];
__device__ __nv_bfloat16 g_wvb  [50048ull*512];
__device__ float g_pmax [NTILES*1248];  // [j][m]
__device__ float g_psum [NTILES*1248];
__device__ float g_pick [1248];
__device__ float g_plogp[1248];

__device__ __forceinline__ float sigf(float x){ return 1.f/(1.f+expf(-x)); }

// ---------------- prep ----------------
__global__ void k_prep(const float* dWih, const float* dWhh, const float* eWif,
                       const float* eWib, const float* Watt){
    size_t stride = (size_t)gridDim.x*blockDim.x;
    size_t id0 = (size_t)blockIdx.x*blockDim.x + threadIdx.x;
    for (size_t i=id0; i<2048ull*1024; i+=stride){
        int n=(int)(i>>10), k=(int)(i&1023);
        g_Wdr[i] = (k<512) ? dWhh[(size_t)n*512+k] : dWih[(size_t)n*768 + 256 + (k-512)];
    }
    for (size_t i=id0; i<2048ull*256; i+=stride){
        int n=(int)(i>>8), k=(int)(i&255);
        g_wifb[i] = __float2bfloat16(eWif[i]);
        g_wibb[i] = __float2bfloat16(eWib[i]);
        g_widb[i] = __float2bfloat16(dWih[(size_t)n*768 + k]);
    }
    for (size_t i=id0; i<512ull*1024; i+=stride) g_wattb[i] = __float2bfloat16(Watt[i]);
    for (size_t i=id0; i<2ull*2*512*32; i+=stride) g_henc[i]=0.f;
    for (size_t i=id0; i<2ull*512*32;   i+=stride) g_cenc[i]=0.f;
    for (size_t i=id0; i<512ull*32;     i+=stride) g_hcat[512*32 + i]=0.f;  // o0=0, buf0
    for (size_t i=id0; i<32ull*512;     i+=stride) g_outsb[1248ull*512+i]=__float2bfloat16(0.f);
    for (size_t i=id0; i<32ull*256;     i+=stride) g_tgteb[1248ull*256+i]=__float2bfloat16(0.f);
    for (size_t i=id0; i<32ull*1024;    i+=stride) g_enchb[1280ull*1024-32768+i]=__float2bfloat16(0.f); // noop-safe
}

__global__ void k_wvb(const float* Wv){
    size_t stride = (size_t)gridDim.x*blockDim.x;
    size_t tot = 50048ull*512/2;
    for (size_t i=(size_t)blockIdx.x*blockDim.x+threadIdx.x; i<tot; i+=stride){
        size_t v = (i*2) >> 9;
        float2 x = (v<50000) ? ((const float2*)Wv)[i] : make_float2(0.f,0.f);
        ((__nv_bfloat162*)g_wvb)[i] = __floats2bfloat162_rn(x.x, x.y);
    }
}

__global__ void k_gather(const int* src, const int* tgt, const float* se, const float* te){
    size_t stride = (size_t)gridDim.x*blockDim.x;
    for (size_t i=(size_t)blockIdx.x*blockDim.x+threadIdx.x; i<(size_t)(1280+1280+1248)*256; i+=stride){
        int k=(int)(i&255); size_t m=i>>8;
        if (m<1280) g_srceb[m*256+k]=__float2bfloat16(se[(size_t)src[m]*256+k]);
        else if (m<2560){
            size_t mm=m-1280; int tt=(int)(mm>>5), bb=(int)(mm&31);
            g_srcerb[mm*256+k]=__float2bfloat16(se[(size_t)src[(39-tt)*32+bb]*256+k]);
        } else {
            size_t mm=m-2560;
            g_tgteb[mm*256+k]=__float2bfloat16(te[(size_t)tgt[mm]*256+k]);
        }
    }
}

// ---------------- smem-staged bf16 GEMM: C[M][N]=A[M][K]@B[N][K]^T ----------------
// MODE 0: C[m*N+n]=v+bias  |  MODE 1: C[((m>>5)*N+n)*32+(m&31)]=v+bias (x layout)
// MODE 2: vocab: per-row max/sumexp partials + picked logit
template<int MODE>
__global__ void __launch_bounds__(256) k_bgemm(const __nv_bfloat16* __restrict__ A,
        const __nv_bfloat16* __restrict__ B, const float* __restrict__ bias,
        float* __restrict__ C, int N, int K, const int* __restrict__ tgt){
    extern __shared__ char sm[];
    __nv_bfloat16 (*As)[48] = (__nv_bfloat16(*)[48])sm;                     // [2*128][48]
    __nv_bfloat16 (*Bs)[48] = (__nv_bfloat16(*)[48])(sm + 2*128*48*2);      // [2*128][48]
    float* scr = (float*)sm;                                                // reuse: [128][132]
    int n0 = blockIdx.x*128, m0 = blockIdx.y*128;
    int tid = threadIdx.x, wp = tid>>5, wm = wp>>2, wn = wp&3;
    int row0 = tid>>2, c8 = (tid&3)*8;
    const __nv_bfloat16* Ag = A + (size_t)m0*K;
    const __nv_bfloat16* Bg = B + (size_t)n0*K;
    wmma::fragment<wmma::matrix_a,16,16,16,__nv_bfloat16,wmma::row_major> af[4];
    wmma::fragment<wmma::matrix_b,16,16,16,__nv_bfloat16,wmma::col_major> bf2[2];
    wmma::fragment<wmma::accumulator,16,16,16,float> cf[4][2];
    #pragma unroll
    for (int i=0;i<4;i++)
        #pragma unroll
        for (int j=0;j<2;j++) wmma::fill_fragment(cf[i][j], 0.f);
    int nch = K>>5;
    uint4 ra0,ra1,rb0,rb1;
    // preload chunk 0
    {
        const __nv_bfloat16* ap = Ag + (size_t)row0*K + c8;
        ra0 = *(const uint4*)ap; ra1 = *(const uint4*)(ap + (size_t)64*K);
        const __nv_bfloat16* bp = Bg + (size_t)row0*K + c8;
        rb0 = *(const uint4*)bp; rb1 = *(const uint4*)(bp + (size_t)64*K);
        *(uint4*)&As[row0][c8]=ra0; *(uint4*)&As[64+row0][c8]=ra1;
        *(uint4*)&Bs[row0][c8]=rb0; *(uint4*)&Bs[64+row0][c8]=rb1;
    }
    for (int c=0;c<nch;c++){
        if (c+1<nch){
            const __nv_bfloat16* ap = Ag + (size_t)row0*K + (c+1)*32 + c8;
            ra0 = *(const uint4*)ap; ra1 = *(const uint4*)(ap + (size_t)64*K);
            const __nv_bfloat16* bp = Bg + (size_t)row0*K + (c+1)*32 + c8;
            rb0 = *(const uint4*)bp; rb1 = *(const uint4*)(bp + (size_t)64*K);
        }
        __syncthreads();
        int bu = (c&1)*128;
        #pragma unroll
        for (int ks=0;ks<2;ks++){
            #pragma unroll
            for (int i=0;i<4;i++) wmma::load_matrix_sync(af[i], &As[bu + wm*64 + i*16][ks*16], 48);
            #pragma unroll
            for (int j=0;j<2;j++) wmma::load_matrix_sync(bf2[j], &Bs[bu + wn*32 + j*16][ks*16], 48);
            #pragma unroll
            for (int i=0;i<4;i++)
                #pragma unroll
                for (int j=0;j<2;j++) wmma::mma_sync(cf[i][j], af[i], bf2[j], cf[i][j]);
        }
        if (c+1<nch){
            int b2 = ((c+1)&1)*128;
            *(uint4*)&As[b2+row0][c8]=ra0; *(uint4*)&As[b2+64+row0][c8]=ra1;
            *(uint4*)&Bs[b2+row0][c8]=rb0; *(uint4*)&Bs[b2+64+row0][c8]=rb1;
        }
    }
    __syncthreads();
    #pragma unroll
    for (int i=0;i<4;i++)
        #pragma unroll
        for (int j=0;j<2;j++)
            wmma::store_matrix_sync(&scr[(wm*64+i*16)*132 + wn*32 + j*16], cf[i][j], 132, wmma::mem_row_major);
    __syncthreads();
    if (MODE == 2){
        if (tid < 128){
            int m = m0 + tid;
            if (m < 1248){
                int v0 = n0;
                int valid = min(128, 50000 - v0);
                float mx = -INFINITY;
                for (int cc=0;cc<valid;cc++) mx = fmaxf(mx, scr[tid*132+cc]);
                float s = 0.f;
                for (int cc=0;cc<valid;cc++) s += expf(scr[tid*132+cc]-mx);
                g_pmax[(size_t)blockIdx.x*1248 + m] = mx;
                g_psum[(size_t)blockIdx.x*1248 + m] = s;
                int tv = tgt[m + 32];
                if (tv >= v0 && tv < v0+valid) g_pick[m] = scr[tid*132 + tv - v0];
            }
        }
    } else {
        for (int idx=tid; idx<128*128; idx+=256){
            int r=idx>>7, cc=idx&127;
            float v = scr[r*132+cc] + (bias ? bias[n0+cc] : 0.f);
            int m = m0+r, n = n0+cc;
            if (MODE == 0) C[(size_t)m*N + n] = v;
            else           C[(((size_t)(m>>5))*N + n)*32 + (m&31)] = v;
        }
    }
}

// ---------------- fp32 GEMM with transposed-out (dec init projections) ----------------
__global__ void __launch_bounds__(256) k_gemm(const float* A, int lda, const float* W, int ldw,
        float* C, int M, int N, int K){
    int m0 = blockIdx.x*64, n0 = blockIdx.y*64;
    int tid = threadIdx.x, tx = tid&15, ty = tid>>4;
    __shared__ float As[64][33], Bs[64][33];
    float acc[4][4] = {};
    for (int k0=0;k0<K;k0+=32){
        #pragma unroll
        for (int p=0;p<8;p++){
            int idx=tid+p*256; int r=idx>>5, kk=idx&31;
            As[r][kk] = (m0+r<M) ? A[(size_t)(m0+r)*lda+k0+kk] : 0.f;
            Bs[r][kk] = (n0+r<N) ? W[(size_t)(n0+r)*ldw+k0+kk] : 0.f;
        }
        __syncthreads();
        #pragma unroll
        for (int kk=0;kk<32;kk++){
            float av[4], bv[4];
            #pragma unroll
            for (int i=0;i<4;i++) av[i]=As[ty*4+i][kk];
            #pragma unroll
            for (int j=0;j<4;j++) bv[j]=Bs[tx*4+j][kk];
            #pragma unroll
            for (int i=0;i<4;i++)
                #pragma unroll
                for (int j=0;j<4;j++) acc[i][j]+=av[i]*bv[j];
        }
        __syncthreads();
    }
    #pragma unroll
    for (int i=0;i<4;i++){
        int m=m0+ty*4+i; if (m>=M) continue;
        #pragma unroll
        for (int j=0;j<4;j++){
            int n=n0+tx*4+j; if (n>=N) continue;
            C[(size_t)n*32 + m] = acc[i][j];   // transposed: [n][b]
        }
    }
}

// ---------------- encoder step: 128 blocks (dir, j-range), coalesced ----------------
__global__ void __launch_bounds__(256) k_enc_step(int t, const float* __restrict__ Whf,
                                                  const float* __restrict__ Whb){
    int blk = blockIdx.x;
    int dir = blk>>6, j0 = (blk&63)*8;
    int tid = threadIdx.x, lane = tid&31, w = tid>>5;
    const float* W = dir ? Whb : Whf;
    int par = t&1;
    const float* hin = g_henc + (size_t)(par*2+dir)*512*32;
    __shared__ float Hs[128][32];
    __shared__ float Ws[32][128];
    float a[4] = {0,0,0,0};
    for (int c=0;c<4;c++){
        #pragma unroll
        for (int p=0;p<16;p++){
            int idx=tid+p*256; int kk=idx>>5, b=idx&31;
            Hs[kk][b] = hin[(size_t)(c*128+kk)*32 + b];
        }
        #pragma unroll
        for (int p=0;p<16;p++){
            int idx=tid+p*256; int r=idx>>7, kk=idx&127;
            Ws[r][kk] = W[(size_t)((r>>3)*512 + j0 + (r&7))*512 + c*128+kk];
        }
        __syncthreads();
        #pragma unroll
        for (int kk=0;kk<128;kk++){
            float h = Hs[kk][lane];
            a[0]+=h*Ws[w][kk]; a[1]+=h*Ws[8+w][kk]; a[2]+=h*Ws[16+w][kk]; a[3]+=h*Ws[24+w][kk];
        }
        __syncthreads();
    }
    int j=j0+w, b=lane;
    const float* xr = (dir?g_xb:g_xf) + (size_t)t*2048*32;
    float gi = sigf (a[0] + xr[(size_t)(      j)*32+b]);
    float gf = sigf (a[1] + xr[(size_t)( 512+j)*32+b]);
    float gg = tanhf(a[2] + xr[(size_t)(1024+j)*32+b]);
    float go = sigf (a[3] + xr[(size_t)(1536+j)*32+b]);
    size_t ci = ((size_t)dir*512+j)*32+b;
    float cn = gf*g_cenc[ci] + gi*gg;
    g_cenc[ci] = cn;
    float hn = go*tanhf(cn);
    g_henc[(((size_t)(1-par)*2+dir)*512 + j)*32 + b] = hn;
    int s = dir ? (39-t) : t;
    size_t eo = ((size_t)b*40+s)*1024 + dir*512 + j;
    g_ench[eo]  = hn;
    g_enchb[eo] = __float2bfloat16(hn);
}

__global__ void k_mkcat(){
    int i = blockIdx.x*blockDim.x + threadIdx.x;
    if (i < 32*1024){
        int b = i>>10, k = i&1023; int dir = k>>9, kk = k&511;
        g_hcc[i] = g_henc[(((size_t)0*2+dir)*512 + kk)*32 + b];
        g_ccc[i] = g_cenc[((size_t)dir*512 + kk)*32 + b];
    }
}

// ---------------- decoder gates + cell fused: 64 blocks ----------------
__global__ void __launch_bounds__(256) k_dgates(int t){
    int j0 = blockIdx.x*8;
    int tid = threadIdx.x, lane = tid&31, w = tid>>5;
    int par = t&1;
    const float* hin = g_hcat + (size_t)par*1024*32;
    __shared__ float Hs[128][32];
    __shared__ float Ws[32][128];
    float a[4] = {0,0,0,0};
    for (int c=0;c<8;c++){
        #pragma unroll
        for (int p=0;p<16;p++){
            int idx=tid+p*256; int kk=idx>>5, b=idx&31;
            Hs[kk][b] = hin[(size_t)(c*128+kk)*32 + b];
        }
        #pragma unroll
        for (int p=0;p<16;p++){
            int idx=tid+p*256; int r=idx>>7, kk=idx&127;
            Ws[r][kk] = g_Wdr[(size_t)((r>>3)*512 + j0 + (r&7))*1024 + c*128+kk];
        }
        __syncthreads();
        #pragma unroll
        for (int kk=0;kk<128;kk++){
            float h = Hs[kk][lane];
            a[0]+=h*Ws[w][kk]; a[1]+=h*Ws[8+w][kk]; a[2]+=h*Ws[16+w][kk]; a[3]+=h*Ws[24+w][kk];
        }
        __syncthreads();
    }
    int j=j0+w, b=lane;
    const float* xr = g_xe + (size_t)t*2048*32;
    float gi = sigf (a[0] + xr[(size_t)(      j)*32+b]);
    float gf = sigf (a[1] + xr[(size_t)( 512+j)*32+b]);
    float gg = tanhf(a[2] + xr[(size_t)(1024+j)*32+b]);
    float go = sigf (a[3] + xr[(size_t)(1536+j)*32+b]);
    size_t ci = (size_t)j*32 + b;
    float cn = gf*g_cdec[ci] + gi*gg;
    g_cdec[ci] = cn;
    float hn = go*tanhf(cn);
    g_kcat[ci] = hn;
    g_hcat[(size_t)(1-par)*1024*32 + ci] = hn;
}

// ---------------- attention: one block per batch ----------------
__global__ void __launch_bounds__(256) k_att(const float* __restrict__ masks){
    int b = blockIdx.x, tid = threadIdx.x, lane = tid&31, w = tid>>5;
    __shared__ float hv[512], sc[40];
    for (int i=tid;i<512;i+=256) hv[i] = g_kcat[(size_t)i*32+b];
    __syncthreads();
    #pragma unroll
    for (int q=0;q<5;q++){
        int s = w*5+q;
        const float* ep = g_encp + ((size_t)b*40+s)*512;
        float p = 0.f;
        for (int k=lane;k<512;k+=32) p += ep[k]*hv[k];
        #pragma unroll
        for (int o=16;o;o>>=1) p += __shfl_down_sync(0xffffffffu, p, o);
        if (!lane) sc[s] = (masks[b*40+s] > 0.f) ? -INFINITY : p;
    }
    __syncthreads();
    if (tid == 0){
        float m = -INFINITY;
        for (int s=0;s<40;s++) m = fmaxf(m, sc[s]);
        float sum = 0.f;
        for (int s=0;s<40;s++){ float e = expf(sc[s]-m); sc[s]=e; sum+=e; }
        float inv = 1.f/sum;
        for (int s=0;s<40;s++) sc[s] *= inv;
    }
    __syncthreads();
    for (int jj=tid;jj<1024;jj+=256){
        float acc = 0.f;
        #pragma unroll 8
        for (int s=0;s<40;s++) acc += sc[s]*g_ench[((size_t)b*40+s)*1024 + jj];
        g_kcat[(size_t)(512+jj)*32 + b] = acc;
    }
}

// ---------------- comb: o_t = tanh([h|ctx]@Wcomb^T), 32 blocks ----------------
__global__ void __launch_bounds__(256) k_comb(int t, const float* __restrict__ Wc){
    int n0 = blockIdx.x*16;
    int tid = threadIdx.x, lane = tid&31, w = tid>>5;
    __shared__ float Hs[128][32];
    __shared__ float Ws[16][128];
    float a0=0.f, a1=0.f;
    for (int c=0;c<12;c++){
        #pragma unroll
        for (int p=0;p<16;p++){
            int idx=tid+p*256; int kk=idx>>5, b=idx&31;
            Hs[kk][b] = g_kcat[(size_t)(c*128+kk)*32 + b];
        }
        #pragma unroll
        for (int p=0;p<8;p++){
            int idx=tid+p*256; int r=idx>>7, kk=idx&127;
            Ws[r][kk] = Wc[(size_t)(n0+r)*1536 + c*128+kk];
        }
        __syncthreads();
        #pragma unroll
        for (int kk=0;kk<128;kk++){
            float h = Hs[kk][lane];
            a0 += h*Ws[w][kk];
            a1 += h*Ws[8+w][kk];
        }
        __syncthreads();
    }
    int par = t&1, b = lane;
    float v0 = tanhf(a0), v1 = tanhf(a1);
    int n = n0 + w;
    float* hc = g_hcat + (size_t)(1-par)*1024*32;
    hc[(size_t)(512+n)*32 + b]   = v0;
    hc[(size_t)(512+n+8)*32 + b] = v1;
    g_outsb[((size_t)t*32+b)*512 + n]   = __float2bfloat16(v0);
    g_outsb[((size_t)t*32+b)*512 + n+8] = __float2bfloat16(v1);
}

// ---------------- final lse combine + output ----------------
__global__ void k_lse(const int* tgt){
    int m = blockIdx.x*blockDim.x + threadIdx.x;
    if (m >= 1248) return;
    float mx = -INFINITY, s = 0.f;
    for (int j=0;j<NTILES;j++){
        float pm = g_pmax[(size_t)j*1248 + m], ps = g_psum[(size_t)j*1248 + m];
        if (pm > mx){ s = s*expf(mx-pm) + ps; mx = pm; }
        else s += ps*expf(pm-mx);
    }
    float lse = mx + logf(s);
    int tv = tgt[m + 32];
    g_plogp[m] = (tv != 0) ? (g_pick[m] - lse) : 0.f;
}

__global__ void k_out(float* out){
    int b = threadIdx.x;
    if (b < 32){
        float s = 0.f;
        for (int t=0;t<39;t++) s += g_plogp[t*32 + b];
        out[b] = s;
    }
}

// ---------------- launch ----------------
extern "C" void kernel_launch(void* const* d_in, const int* in_sizes, int n_in,
                              void* d_out, int out_size){
    const int*   src   = (const int*)d_in[0];
    const int*   tgt   = (const int*)d_in[1];
    const float* masks = (const float*)d_in[2];
    const float* se    = (const float*)d_in[3];
    const float* te    = (const float*)d_in[4];
    const float* eWif  = (const float*)d_in[5];
    const float* eWhf  = (const float*)d_in[6];
    const float* ebf   = (const float*)d_in[7];
    const float* eWib  = (const float*)d_in[8];
    const float* eWhb  = (const float*)d_in[9];
    const float* ebb   = (const float*)d_in[10];
    const float* dWih  = (const float*)d_in[11];
    const float* dWhh  = (const float*)d_in[12];
    const float* db    = (const float*)d_in[13];
    const float* Wh    = (const float*)d_in[14];
    const float* Wc    = (const float*)d_in[15];
    const float* Watt  = (const float*)d_in[16];
    const float* Wcomb = (const float*)d_in[17];
    const float* Wv    = (const float*)d_in[18];

    __nv_bfloat16 *p_srceb,*p_srcerb,*p_tgteb,*p_wifb,*p_wibb,*p_widb,*p_wattb,*p_enchb,*p_wvb,*p_outsb;
    float *p_xf,*p_xb,*p_xe,*p_encp,*p_hcc,*p_ccc,*p_hcat,*p_cdec;
    cudaGetSymbolAddress((void**)&p_srceb,  g_srceb);
    cudaGetSymbolAddress((void**)&p_srcerb, g_srcerb);
    cudaGetSymbolAddress((void**)&p_tgteb,  g_tgteb);
    cudaGetSymbolAddress((void**)&p_wifb,   g_wifb);
    cudaGetSymbolAddress((void**)&p_wibb,   g_wibb);
    cudaGetSymbolAddress((void**)&p_widb,   g_widb);
    cudaGetSymbolAddress((void**)&p_wattb,  g_wattb);
    cudaGetSymbolAddress((void**)&p_enchb,  g_enchb);
    cudaGetSymbolAddress((void**)&p_wvb,    g_wvb);
    cudaGetSymbolAddress((void**)&p_outsb,  g_outsb);
    cudaGetSymbolAddress((void**)&p_xf,     g_xf);
    cudaGetSymbolAddress((void**)&p_xb,     g_xb);
    cudaGetSymbolAddress((void**)&p_xe,     g_xe);
    cudaGetSymbolAddress((void**)&p_encp,   g_encp);
    cudaGetSymbolAddress((void**)&p_hcc,    g_hcc);
    cudaGetSymbolAddress((void**)&p_ccc,    g_ccc);
    cudaGetSymbolAddress((void**)&p_hcat,   g_hcat);
    cudaGetSymbolAddress((void**)&p_cdec,   g_cdec);

    const int SMEM = 128*132*4;  // 67584
    cudaFuncSetAttribute(k_bgemm<0>, cudaFuncAttributeMaxDynamicSharedMemorySize, SMEM);
    cudaFuncSetAttribute(k_bgemm<1>, cudaFuncAttributeMaxDynamicSharedMemorySize, SMEM);
    cudaFuncSetAttribute(k_bgemm<2>, cudaFuncAttributeMaxDynamicSharedMemorySize, SMEM);

    k_prep<<<1024,256>>>(dWih, dWhh, eWif, eWib, Watt);
    k_wvb<<<2048,256>>>(Wv);
    k_gather<<<512,256>>>(src, tgt, se, te);

    // input-side GEMMs (bf16 tensor cores, x written transposed [t][2048][32])
    k_bgemm<1><<<dim3(16,10),256,SMEM>>>(p_srceb,  p_wifb, ebf, p_xf, 2048, 256, nullptr);
    k_bgemm<1><<<dim3(16,10),256,SMEM>>>(p_srcerb, p_wibb, ebb, p_xb, 2048, 256, nullptr);
    k_bgemm<1><<<dim3(16,10),256,SMEM>>>(p_tgteb,  p_widb, db,  p_xe, 2048, 256, nullptr);

    for (int t=0;t<40;t++) k_enc_step<<<128,256>>>(t, eWhf, eWhb);

    k_mkcat<<<128,256>>>();
    k_gemm<<<dim3(1,8),256>>>(p_hcc, 1024, Wh, 1024, p_hcat, 32, 512, 1024);
    k_gemm<<<dim3(1,8),256>>>(p_ccc, 1024, Wc, 1024, p_cdec, 32, 512, 1024);
    k_bgemm<0><<<dim3(4,10),256,SMEM>>>(p_enchb, p_wattb, nullptr, p_encp, 512, 1024, nullptr);

    for (int t=0;t<39;t++){
        k_dgates<<<64,256>>>(t);
        k_att<<<32,256>>>(masks);
        k_comb<<<32,256>>>(t, Wcomb);
    }

    k_bgemm<2><<<dim3(NTILES,10),256,SMEM>>>(p_outsb, p_wvb, nullptr, nullptr, 50048, 512, tgt);
    k_lse<<<10,128>>>(tgt);
    k_out<<<1,32>>>((float*)d_out);
}

// round 5
// speedup vs baseline: 2.9146x; 1.6603x over previous
#include <cuda_runtime.h>
#include <cuda_bf16.h>
#include <mma.h>
#include <math.h>
#include <stdint.h>

using namespace nvcuda;

// S=40, B=32, T=40, E=256, H=512, V=50000; decoder rows 1248 (pad 1280)
#define NTILES 391

#define CPA16(sdst, gsrc) asm volatile("cp.async.cg.shared.global [%0], [%1], 16;\n" :: "r"(sdst), "l"(gsrc))
#define CPCOMMIT() asm volatile("cp.async.commit_group;\n" ::: "memory")
#define CPWAIT1() asm volatile("cp.async.wait_group 1;\n" ::: "memory")
#define CPWAIT0() asm volatile("cp.async.wait_group 0;\n" ::: "memory")

// ---------------- static device scratch ----------------
__device__ __nv_bfloat16 g_srceb [1280*256];
__device__ __nv_bfloat16 g_srcerb[1280*256];
__device__ __nv_bfloat16 g_tgteb [1280*256];
__device__ __nv_bfloat16 g_wifb  [2048*256];
__device__ __nv_bfloat16 g_wibb  [2048*256];
__device__ __nv_bfloat16 g_widb  [2048*256];
__device__ __nv_bfloat16 g_wattb [512*1024];
__device__ float g_xf   [40*2048*32];   // [t][2048][32]
__device__ float g_xb   [40*2048*32];
__device__ float g_xe   [40*2048*32];
__device__ float g_henc [2*2*512*32];   // [par][dir][512][32]
__device__ float g_cenc [2*512*32];     // [dir][512][32]
__device__ float g_ench [32*40*1024];   // [b][s][2H] fp32 (for ctx)
__device__ __nv_bfloat16 g_enchb[1280*1024]; // rows m=b*40+s
__device__ float g_encp [1280*512];     // rows m=b*40+s
__device__ float g_hcc  [32*1024];
__device__ float g_ccc  [32*1024];
__device__ float g_hcat [2*1024*32];    // [par][ h(512)|o_prev(512) ][32]
__device__ float g_cdec [512*32];
__device__ float g_kcat [1536*32];      // [ h(512)|ctx(1024) ][32]
__device__ float g_Wdr  [2048*1024];    // [Whh | Wih_o]
__device__ __nv_bfloat16 g_outsb[1280*512];
__device__ __nv_bfloat16 g_wvb  [50048ull*512];
__device__ float g_pmax [NTILES*1280];  // [j][m]
__device__ float g_psum [NTILES*1280];
__device__ float g_pick [1248];
__device__ float g_plogp[1248];

__device__ __forceinline__ float sigf(float x){ return 1.f/(1.f+expf(-x)); }

// ---------------- prep ----------------
__global__ void k_prep(const float* dWih, const float* dWhh, const float* eWif,
                       const float* eWib, const float* Watt){
    size_t stride = (size_t)gridDim.x*blockDim.x;
    size_t id0 = (size_t)blockIdx.x*blockDim.x + threadIdx.x;
    for (size_t i=id0; i<2048ull*1024; i+=stride){
        int n=(int)(i>>10), k=(int)(i&1023);
        g_Wdr[i] = (k<512) ? dWhh[(size_t)n*512+k] : dWih[(size_t)n*768 + 256 + (k-512)];
    }
    for (size_t i=id0; i<2048ull*256; i+=stride){
        int n=(int)(i>>8), k=(int)(i&255);
        g_wifb[i] = __float2bfloat16(eWif[i]);
        g_wibb[i] = __float2bfloat16(eWib[i]);
        g_widb[i] = __float2bfloat16(dWih[(size_t)n*768 + k]);
    }
    for (size_t i=id0; i<512ull*1024; i+=stride) g_wattb[i] = __float2bfloat16(Watt[i]);
    for (size_t i=id0; i<2ull*2*512*32; i+=stride) g_henc[i]=0.f;
    for (size_t i=id0; i<2ull*512*32;   i+=stride) g_cenc[i]=0.f;
    for (size_t i=id0; i<512ull*32;     i+=stride) g_hcat[512*32 + i]=0.f;  // o0=0, buf0
    for (size_t i=id0; i<32ull*512;     i+=stride) g_outsb[1248ull*512+i]=__float2bfloat16(0.f);
    for (size_t i=id0; i<32ull*256;     i+=stride) g_tgteb[1248ull*256+i]=__float2bfloat16(0.f);
}

__global__ void k_wvb(const float* Wv){
    size_t stride = (size_t)gridDim.x*blockDim.x;
    size_t tot = 50048ull*512/2;
    for (size_t i=(size_t)blockIdx.x*blockDim.x+threadIdx.x; i<tot; i+=stride){
        size_t v = (i*2) >> 9;
        float2 x = (v<50000) ? ((const float2*)Wv)[i] : make_float2(0.f,0.f);
        ((__nv_bfloat162*)g_wvb)[i] = __floats2bfloat162_rn(x.x, x.y);
    }
}

__global__ void k_gather(const int* src, const int* tgt, const float* se, const float* te){
    size_t stride = (size_t)gridDim.x*blockDim.x;
    for (size_t i=(size_t)blockIdx.x*blockDim.x+threadIdx.x; i<(size_t)(1280+1280+1248)*256; i+=stride){
        int k=(int)(i&255); size_t m=i>>8;
        if (m<1280) g_srceb[m*256+k]=__float2bfloat16(se[(size_t)src[m]*256+k]);
        else if (m<2560){
            size_t mm=m-1280; int tt=(int)(mm>>5), bb=(int)(mm&31);
            g_srcerb[mm*256+k]=__float2bfloat16(se[(size_t)src[(39-tt)*32+bb]*256+k]);
        } else {
            size_t mm=m-2560;
            g_tgteb[mm*256+k]=__float2bfloat16(te[(size_t)tgt[mm]*256+k]);
        }
    }
}

// ---------------- pipelined bf16 GEMM: C[M][N]=A[M][K]@B[N][K]^T ----------------
// MODE 0: C[m*N+n]=v+bias | MODE 1: C[((m>>5)*N+n)*32+(m&31)]=v+bias | MODE 2: vocab lse partials
template<int MODE>
__global__ void __launch_bounds__(256) k_bgemm(const __nv_bfloat16* __restrict__ A,
        const __nv_bfloat16* __restrict__ B, const float* __restrict__ bias,
        float* __restrict__ C, int N, int K, const int* __restrict__ tgt){
    extern __shared__ char sm[];
    const int LD = 72;
    __nv_bfloat16* As = (__nv_bfloat16*)sm;                  // [2][128][72]
    __nv_bfloat16* Bs = (__nv_bfloat16*)(sm + 2*128*LD*2);   // [2][128][72]
    float* scr = (float*)sm;                                  // reuse [128][132]
    int n0 = blockIdx.x*128, m0 = blockIdx.y*128;
    int tid = threadIdx.x, wp = tid>>5, wm = wp>>2, wn = wp&3;
    wmma::fragment<wmma::matrix_a,16,16,16,__nv_bfloat16,wmma::row_major> af[4];
    wmma::fragment<wmma::matrix_b,16,16,16,__nv_bfloat16,wmma::col_major> bf2[2];
    wmma::fragment<wmma::accumulator,16,16,16,float> cf[4][2];
    #pragma unroll
    for (int i=0;i<4;i++)
        #pragma unroll
        for (int j=0;j<2;j++) wmma::fill_fragment(cf[i][j], 0.f);
    int nch = K>>6;
    int row = tid>>3, seg = tid&7;   // we load 4 (row,seg) pairs: rows row, row+32, row+64, row+96
    auto issue = [&](int c, int st){
        #pragma unroll
        for (int i=0;i<4;i++){
            int r = row + i*32;
            const __nv_bfloat16* ga = A + (size_t)(m0+r)*K + c*64 + seg*8;
            unsigned sa = (unsigned)__cvta_generic_to_shared(As + (st*128+r)*LD + seg*8);
            CPA16(sa, ga);
            const __nv_bfloat16* gb = B + (size_t)(n0+r)*K + c*64 + seg*8;
            unsigned sb = (unsigned)__cvta_generic_to_shared(Bs + (st*128+r)*LD + seg*8);
            CPA16(sb, gb);
        }
    };
    issue(0,0); CPCOMMIT();
    for (int c=0;c<nch;c++){
        int st = c&1;
        if (c+1<nch){ issue(c+1, st^1); CPCOMMIT(); CPWAIT1(); }
        else        { CPWAIT0(); }
        __syncthreads();
        #pragma unroll
        for (int ks=0;ks<4;ks++){
            #pragma unroll
            for (int i=0;i<4;i++)
                wmma::load_matrix_sync(af[i], As + (size_t)(st*128 + wm*64 + i*16)*LD + ks*16, LD);
            #pragma unroll
            for (int j=0;j<2;j++)
                wmma::load_matrix_sync(bf2[j], Bs + (size_t)(st*128 + wn*32 + j*16)*LD + ks*16, LD);
            #pragma unroll
            for (int i=0;i<4;i++)
                #pragma unroll
                for (int j=0;j<2;j++) wmma::mma_sync(cf[i][j], af[i], bf2[j], cf[i][j]);
        }
        __syncthreads();
    }
    #pragma unroll
    for (int i=0;i<4;i++)
        #pragma unroll
        for (int j=0;j<2;j++)
            wmma::store_matrix_sync(&scr[(wm*64+i*16)*132 + wn*32 + j*16], cf[i][j], 132, wmma::mem_row_major);
    __syncthreads();
    if (MODE == 2){
        int r = tid>>1, hh = tid&1;
        int m = m0 + r;
        if (m < 1248){
            int valid = min(128, 50000 - n0);
            int c0 = hh*64, c1 = min(c0+64, valid);
            float mx = -INFINITY, s = 0.f;
            for (int cc=c0; cc<c1; cc++) mx = fmaxf(mx, scr[r*132+cc]);
            for (int cc=c0; cc<c1; cc++) s += expf(scr[r*132+cc]-mx);
            float mo = __shfl_xor_sync(0xffffffffu, mx, 1);
            float so = __shfl_xor_sync(0xffffffffu, s, 1);
            float M = fmaxf(mx, mo);
            float S = ((mx == -INFINITY) ? 0.f : s*expf(mx-M)) +
                      ((mo == -INFINITY) ? 0.f : so*expf(mo-M));
            if (hh == 0){
                g_pmax[(size_t)blockIdx.x*1280 + m] = M;
                g_psum[(size_t)blockIdx.x*1280 + m] = S;
            }
            int tv = tgt[m + 32];
            int lv = tv - n0;
            if (lv >= c0 && lv < c1) g_pick[m] = scr[r*132 + lv];
        }
    } else {
        for (int idx=tid; idx<128*128; idx+=256){
            int r=idx>>7, cc=idx&127;
            float v = scr[r*132+cc] + (bias ? bias[n0+cc] : 0.f);
            int m = m0+r, n = n0+cc;
            if (MODE == 0) C[(size_t)m*N + n] = v;
            else           C[(((size_t)(m>>5))*N + n)*32 + (m&31)] = v;
        }
    }
}

// ---------------- fp32 GEMM transposed-out (decoder init projections) ----------------
__global__ void __launch_bounds__(256) k_gemm(const float* A, int lda, const float* W, int ldw,
        float* C, int M, int N, int K){
    int m0 = blockIdx.x*64, n0 = blockIdx.y*64;
    int tid = threadIdx.x, tx = tid&15, ty = tid>>4;
    __shared__ float As[64][33], Bs[64][33];
    float acc[4][4] = {};
    for (int k0=0;k0<K;k0+=32){
        #pragma unroll
        for (int p=0;p<8;p++){
            int idx=tid+p*256; int r=idx>>5, kk=idx&31;
            As[r][kk] = (m0+r<M) ? A[(size_t)(m0+r)*lda+k0+kk] : 0.f;
            Bs[r][kk] = (n0+r<N) ? W[(size_t)(n0+r)*ldw+k0+kk] : 0.f;
        }
        __syncthreads();
        #pragma unroll
        for (int kk=0;kk<32;kk++){
            float av[4], bv[4];
            #pragma unroll
            for (int i=0;i<4;i++) av[i]=As[ty*4+i][kk];
            #pragma unroll
            for (int j=0;j<4;j++) bv[j]=Bs[tx*4+j][kk];
            #pragma unroll
            for (int i=0;i<4;i++)
                #pragma unroll
                for (int j=0;j<4;j++) acc[i][j]+=av[i]*bv[j];
        }
        __syncthreads();
    }
    #pragma unroll
    for (int i=0;i<4;i++){
        int m=m0+ty*4+i; if (m>=M) continue;
        #pragma unroll
        for (int j=0;j<4;j++){
            int n=n0+tx*4+j; if (n>=N) continue;
            C[(size_t)n*32 + m] = acc[i][j];   // transposed: [n][b]
        }
    }
}

// ---------------- encoder step: 128 blocks, register-tiled, split-K(4) in block ----------------
// smem: Hs[512][32] (64KB) | Ws[32][512] (64KB) | Rs[4][8][4][32] (16KB)
__global__ void __launch_bounds__(256) k_enc_step(int t, const float* __restrict__ Whf,
                                                  const float* __restrict__ Whb){
    extern __shared__ float smf[];
    float* Hs = smf;
    float* Ws = smf + 512*32;
    float* Rs = smf + 512*32 + 32*512;
    int blk = blockIdx.x, tid = threadIdx.x;
    int dir = blk>>6, j0 = (blk&63)*8;
    const float* W = dir ? Whb : Whf;
    int par = t&1;
    const float* hin = g_henc + (size_t)(par*2+dir)*512*32;
    #pragma unroll
    for (int p=0;p<16;p++){
        int idx = tid + p*256;
        ((float4*)Hs)[idx] = ((const float4*)hin)[idx];
        int r = idx>>7, q4 = idx&127;
        int grow = (r>>3)*512 + j0 + (r&7);
        ((float4*)(Ws + r*512))[q4] = ((const float4*)(W + (size_t)grow*512))[q4];
    }
    __syncthreads();
    int tx = tid&7, jj = (tid>>3)&7, sl = tid>>6;
    int b0 = tx*4;
    float a[4][4] = {};
    int kbeg = sl*128;
    #pragma unroll 4
    for (int kk=kbeg; kk<kbeg+128; kk++){
        float4 h = *(const float4*)&Hs[kk*32 + b0];
        #pragma unroll
        for (int g=0; g<4; g++){
            float w = Ws[(g*8+jj)*512 + kk];
            a[g][0] += w*h.x; a[g][1] += w*h.y; a[g][2] += w*h.z; a[g][3] += w*h.w;
        }
    }
    #pragma unroll
    for (int g=0; g<4; g++)
        #pragma unroll
        for (int i=0;i<4;i++)
            Rs[((sl*8+jj)*4+g)*32 + b0+i] = a[g][i];
    __syncthreads();
    {
        int j = tid>>5, b = tid&31;
        float gg4[4];
        #pragma unroll
        for (int g=0; g<4; g++){
            float s = 0.f;
            #pragma unroll
            for (int s4=0; s4<4; s4++) s += Rs[((s4*8+j)*4+g)*32 + b];
            gg4[g] = s;
        }
        int jg = j0 + j;
        const float* xr = (dir?g_xb:g_xf) + (size_t)t*2048*32;
        float gi = sigf (gg4[0] + xr[(size_t)(      jg)*32+b]);
        float gf = sigf (gg4[1] + xr[(size_t)( 512+jg)*32+b]);
        float gc = tanhf(gg4[2] + xr[(size_t)(1024+jg)*32+b]);
        float go = sigf (gg4[3] + xr[(size_t)(1536+jg)*32+b]);
        size_t ci = ((size_t)dir*512+jg)*32+b;
        float cn = gf*g_cenc[ci] + gi*gc;
        g_cenc[ci] = cn;
        float hn = go*tanhf(cn);
        g_henc[(((size_t)(1-par)*2+dir)*512 + jg)*32 + b] = hn;
        int s = dir ? (39-t) : t;
        size_t eo = ((size_t)b*40+s)*1024 + dir*512 + jg;
        g_ench[eo]  = hn;
        g_enchb[eo] = __float2bfloat16(hn);
    }
}

__global__ void k_mkcat(){
    int i = blockIdx.x*blockDim.x + threadIdx.x;
    if (i < 32*1024){
        int b = i>>10, k = i&1023; int dir = k>>9, kk = k&511;
        g_hcc[i] = g_henc[(((size_t)0*2+dir)*512 + kk)*32 + b];
        g_ccc[i] = g_cenc[((size_t)dir*512 + kk)*32 + b];
    }
}

// ---------------- decoder gates+cell: 128 blocks, split-K(8), K=1024 in 2 chunks ----------------
// smem: Hs[512][32] (64KB) | Ws[16][1024] (64KB) | Rs[8][4][4][32] (16KB)
__global__ void __launch_bounds__(256) k_dgates(int t){
    extern __shared__ float smf[];
    float* Hs = smf;
    float* Ws = smf + 512*32;
    float* Rs = smf + 512*32 + 16*1024;
    int blk = blockIdx.x, tid = threadIdx.x;
    int j0 = blk*4;
    int par = t&1;
    const float* hin = g_hcat + (size_t)par*1024*32;
    // Ws full: 16 rows x 1024
    #pragma unroll
    for (int p=0;p<16;p++){
        int idx = tid + p*256;
        int r = idx>>8, q4 = idx&255;
        int grow = (r>>2)*512 + j0 + (r&3);
        ((float4*)(Ws + r*1024))[q4] = ((const float4*)(g_Wdr + (size_t)grow*1024))[q4];
    }
    int tx = tid&7, jj = (tid>>3)&3, sl = tid>>5;
    int b0 = tx*4;
    float a[4][4] = {};
    for (int c=0;c<2;c++){
        __syncthreads();
        #pragma unroll
        for (int p=0;p<16;p++){
            int idx = tid + p*256;
            ((float4*)Hs)[idx] = ((const float4*)(hin + (size_t)c*512*32))[idx];
        }
        __syncthreads();
        int kbeg = sl*64;
        #pragma unroll 4
        for (int kk=kbeg; kk<kbeg+64; kk++){
            float4 h = *(const float4*)&Hs[kk*32 + b0];
            int kg = c*512 + kk;
            #pragma unroll
            for (int g=0; g<4; g++){
                float w = Ws[(g*4+jj)*1024 + kg];
                a[g][0] += w*h.x; a[g][1] += w*h.y; a[g][2] += w*h.z; a[g][3] += w*h.w;
            }
        }
    }
    #pragma unroll
    for (int g=0; g<4; g++)
        #pragma unroll
        for (int i=0;i<4;i++)
            Rs[((sl*4+jj)*4+g)*32 + b0+i] = a[g][i];
    __syncthreads();
    if (tid < 128){
        int j = tid>>5, b = tid&31;
        float gg4[4];
        #pragma unroll
        for (int g=0; g<4; g++){
            float s = 0.f;
            #pragma unroll
            for (int s8=0; s8<8; s8++) s += Rs[((s8*4+j)*4+g)*32 + b];
            gg4[g] = s;
        }
        int jg = j0 + j;
        const float* xr = g_xe + (size_t)t*2048*32;
        float gi = sigf (gg4[0] + xr[(size_t)(      jg)*32+b]);
        float gf = sigf (gg4[1] + xr[(size_t)( 512+jg)*32+b]);
        float gc = tanhf(gg4[2] + xr[(size_t)(1024+jg)*32+b]);
        float go = sigf (gg4[3] + xr[(size_t)(1536+jg)*32+b]);
        size_t ci = (size_t)jg*32 + b;
        float cn = gf*g_cdec[ci] + gi*gc;
        g_cdec[ci] = cn;
        float hn = go*tanhf(cn);
        g_kcat[ci] = hn;
        g_hcat[(size_t)(1-par)*1024*32 + ci] = hn;
    }
}

// ---------------- attention: one block per batch ----------------
__global__ void __launch_bounds__(256) k_att(const float* __restrict__ masks){
    int b = blockIdx.x, tid = threadIdx.x, lane = tid&31, w = tid>>5;
    __shared__ float hv[512], sc[40];
    for (int i=tid;i<512;i+=256) hv[i] = g_kcat[(size_t)i*32+b];
    __syncthreads();
    #pragma unroll
    for (int q=0;q<5;q++){
        int s = w*5+q;
        const float* ep = g_encp + ((size_t)b*40+s)*512;
        float p = 0.f;
        for (int k=lane;k<512;k+=32) p += ep[k]*hv[k];
        #pragma unroll
        for (int o=16;o;o>>=1) p += __shfl_down_sync(0xffffffffu, p, o);
        if (!lane) sc[s] = (masks[b*40+s] > 0.f) ? -INFINITY : p;
    }
    __syncthreads();
    if (tid == 0){
        float m = -INFINITY;
        for (int s=0;s<40;s++) m = fmaxf(m, sc[s]);
        float sum = 0.f;
        for (int s=0;s<40;s++){ float e = expf(sc[s]-m); sc[s]=e; sum+=e; }
        float inv = 1.f/sum;
        for (int s=0;s<40;s++) sc[s] *= inv;
    }
    __syncthreads();
    for (int jj=tid;jj<1024;jj+=256){
        float acc = 0.f;
        #pragma unroll 8
        for (int s=0;s<40;s++) acc += sc[s]*g_ench[((size_t)b*40+s)*1024 + jj];
        g_kcat[(size_t)(512+jj)*32 + b] = acc;
    }
}

// ---------------- comb: 128 blocks, split-K(8), K=1536 in 3 chunks ----------------
// smem: Hs[512][32] (64KB) | Ws[4][1536] (24KB) | Rs[8][4][32] (4KB)
__global__ void __launch_bounds__(256) k_comb(int t, const float* __restrict__ Wc){
    extern __shared__ float smf[];
    float* Hs = smf;
    float* Ws = smf + 512*32;
    float* Rs = smf + 512*32 + 4*1536;
    int blk = blockIdx.x, tid = threadIdx.x;
    int j0 = blk*4;
    #pragma unroll
    for (int p=0;p<6;p++){
        int idx = tid + p*256;
        int r = idx/384, q4 = idx%384;
        ((float4*)(Ws + r*1536))[q4] = ((const float4*)(Wc + (size_t)(j0+r)*1536))[q4];
    }
    int tx = tid&7, jj = (tid>>3)&3, sl = tid>>5;
    int b0 = tx*4;
    float a[4] = {0,0,0,0};
    for (int c=0;c<3;c++){
        __syncthreads();
        #pragma unroll
        for (int p=0;p<16;p++){
            int idx = tid + p*256;
            ((float4*)Hs)[idx] = ((const float4*)(g_kcat + (size_t)c*512*32))[idx];
        }
        __syncthreads();
        int kbeg = sl*64;
        #pragma unroll 4
        for (int kk=kbeg; kk<kbeg+64; kk++){
            float4 h = *(const float4*)&Hs[kk*32 + b0];
            float w = Ws[jj*1536 + c*512 + kk];
            a[0] += w*h.x; a[1] += w*h.y; a[2] += w*h.z; a[3] += w*h.w;
        }
    }
    #pragma unroll
    for (int i=0;i<4;i++) Rs[(sl*4+jj)*32 + b0+i] = a[i];
    __syncthreads();
    if (tid < 128){
        int j = tid>>5, b = tid&31;
        float s = 0.f;
        #pragma unroll
        for (int s8=0; s8<8; s8++) s += Rs[(s8*4+j)*32 + b];
        float v = tanhf(s);
        int n = j0 + j;
        int par = t&1;
        g_hcat[(size_t)(1-par)*1024*32 + (size_t)(512+n)*32 + b] = v;
        g_outsb[((size_t)t*32+b)*512 + n] = __float2bfloat16(v);
    }
}

// ---------------- final lse combine + output ----------------
__global__ void k_lse(const int* tgt){
    int m = blockIdx.x*blockDim.x + threadIdx.x;
    if (m >= 1248) return;
    float mx = -INFINITY, s = 0.f;
    for (int j=0;j<NTILES;j++){
        float pm = g_pmax[(size_t)j*1280 + m], ps = g_psum[(size_t)j*1280 + m];
        if (pm > mx){ s = s*expf(mx-pm) + ps; mx = pm; }
        else s += ps*expf(pm-mx);
    }
    float lse = mx + logf(s);
    int tv = tgt[m + 32];
    g_plogp[m] = (tv != 0) ? (g_pick[m] - lse) : 0.f;
}

__global__ void k_out(float* out){
    int b = threadIdx.x;
    if (b < 32){
        float s = 0.f;
        for (int t=0;t<39;t++) s += g_plogp[t*32 + b];
        out[b] = s;
    }
}

// ---------------- launch ----------------
extern "C" void kernel_launch(void* const* d_in, const int* in_sizes, int n_in,
                              void* d_out, int out_size){
    const int*   src   = (const int*)d_in[0];
    const int*   tgt   = (const int*)d_in[1];
    const float* masks = (const float*)d_in[2];
    const float* se    = (const float*)d_in[3];
    const float* te    = (const float*)d_in[4];
    const float* eWif  = (const float*)d_in[5];
    const float* eWhf  = (const float*)d_in[6];
    const float* ebf   = (const float*)d_in[7];
    const float* eWib  = (const float*)d_in[8];
    const float* eWhb  = (const float*)d_in[9];
    const float* ebb   = (const float*)d_in[10];
    const float* dWih  = (const float*)d_in[11];
    const float* dWhh  = (const float*)d_in[12];
    const float* db    = (const float*)d_in[13];
    const float* Wh    = (const float*)d_in[14];
    const float* Wc    = (const float*)d_in[15];
    const float* Watt  = (const float*)d_in[16];
    const float* Wcomb = (const float*)d_in[17];
    const float* Wv    = (const float*)d_in[18];

    __nv_bfloat16 *p_srceb,*p_srcerb,*p_tgteb,*p_wifb,*p_wibb,*p_widb,*p_wattb,*p_enchb,*p_wvb,*p_outsb;
    float *p_xf,*p_xb,*p_xe,*p_encp,*p_hcc,*p_ccc,*p_hcat,*p_cdec;
    cudaGetSymbolAddress((void**)&p_srceb,  g_srceb);
    cudaGetSymbolAddress((void**)&p_srcerb, g_srcerb);
    cudaGetSymbolAddress((void**)&p_tgteb,  g_tgteb);
    cudaGetSymbolAddress((void**)&p_wifb,   g_wifb);
    cudaGetSymbolAddress((void**)&p_wibb,   g_wibb);
    cudaGetSymbolAddress((void**)&p_widb,   g_widb);
    cudaGetSymbolAddress((void**)&p_wattb,  g_wattb);
    cudaGetSymbolAddress((void**)&p_enchb,  g_enchb);
    cudaGetSymbolAddress((void**)&p_wvb,    g_wvb);
    cudaGetSymbolAddress((void**)&p_outsb,  g_outsb);
    cudaGetSymbolAddress((void**)&p_xf,     g_xf);
    cudaGetSymbolAddress((void**)&p_xb,     g_xb);
    cudaGetSymbolAddress((void**)&p_xe,     g_xe);
    cudaGetSymbolAddress((void**)&p_encp,   g_encp);
    cudaGetSymbolAddress((void**)&p_hcc,    g_hcc);
    cudaGetSymbolAddress((void**)&p_ccc,    g_ccc);
    cudaGetSymbolAddress((void**)&p_hcat,   g_hcat);
    cudaGetSymbolAddress((void**)&p_cdec,   g_cdec);

    const int SM_GEMM = 2*2*128*72*2;          // 73728
    const int SM_ENC  = (512*32 + 32*512 + 4*8*4*32)*4;   // 147456
    const int SM_DG   = (512*32 + 16*1024 + 8*4*4*32)*4;  // 147456
    const int SM_CB   = (512*32 + 4*1536 + 8*4*32)*4;     // 94208
    cudaFuncSetAttribute(k_bgemm<0>, cudaFuncAttributeMaxDynamicSharedMemorySize, SM_GEMM);
    cudaFuncSetAttribute(k_bgemm<1>, cudaFuncAttributeMaxDynamicSharedMemorySize, SM_GEMM);
    cudaFuncSetAttribute(k_bgemm<2>, cudaFuncAttributeMaxDynamicSharedMemorySize, SM_GEMM);
    cudaFuncSetAttribute(k_enc_step, cudaFuncAttributeMaxDynamicSharedMemorySize, SM_ENC);
    cudaFuncSetAttribute(k_dgates,   cudaFuncAttributeMaxDynamicSharedMemorySize, SM_DG);
    cudaFuncSetAttribute(k_comb,     cudaFuncAttributeMaxDynamicSharedMemorySize, SM_CB);

    k_prep<<<1024,256>>>(dWih, dWhh, eWif, eWib, Watt);
    k_wvb<<<2048,256>>>(Wv);
    k_gather<<<512,256>>>(src, tgt, se, te);

    // input-side GEMMs (x written transposed [t][2048][32])
    k_bgemm<1><<<dim3(16,10),256,SM_GEMM>>>(p_srceb,  p_wifb, ebf, p_xf, 2048, 256, nullptr);
    k_bgemm<1><<<dim3(16,10),256,SM_GEMM>>>(p_srcerb, p_wibb, ebb, p_xb, 2048, 256, nullptr);
    k_bgemm<1><<<dim3(16,10),256,SM_GEMM>>>(p_tgteb,  p_widb, db,  p_xe, 2048, 256, nullptr);

    for (int t=0;t<40;t++) k_enc_step<<<128,256,SM_ENC>>>(t, eWhf, eWhb);

    k_mkcat<<<128,256>>>();
    k_gemm<<<dim3(1,8),256>>>(p_hcc, 1024, Wh, 1024, p_hcat, 32, 512, 1024);
    k_gemm<<<dim3(1,8),256>>>(p_ccc, 1024, Wc, 1024, p_cdec, 32, 512, 1024);
    k_bgemm<0><<<dim3(4,10),256,SM_GEMM>>>(p_enchb, p_wattb, nullptr, p_encp, 512, 1024, nullptr);

    for (int t=0;t<39;t++){
        k_dgates<<<128,256,SM_DG>>>(t);
        k_att<<<32,256>>>(masks);
        k_comb<<<128,256,SM_CB>>>(t, Wcomb);
    }

    k_bgemm<2><<<dim3(NTILES,10),256,SM_GEMM>>>(p_outsb, p_wvb, nullptr, nullptr, 50048, 512, tgt);
    k_lse<<<10,128>>>(tgt);
    k_out<<<1,32>>>((float*)d_out);
}